// round 14
// baseline (speedup 1.0000x reference)
#include <cuda_runtime.h>
#include <math.h>

#define FULLMASK 0xffffffffu
constexpr int B_ = 32, N_ = 16384, M_ = 128, PW = 86, NLOG = 80;
constexpr int TPB = 512;
constexpr int REPS = 2;                         // preds per thread
constexpr int CHUNK = TPB * REPS;               // 1024 preds per block
constexpr int BLKX = N_ / CHUNK;                // 16 chunks per image
constexpr int NWARP = TPB / 32;                 // 16
constexpr float NEGV = -1000000000.0f;

// per-(image,chunk) partials:
// [0]=n_m [1]=s_bbox [2]=s_nll [3]=s_bce1 [4]=s_bce0_unmatched [5]=s_bce0_all
// [6]=fb_max [7]=fb_n [8]=fb_bbox [9]=fb_nll [10]=fb_bce1 [11]=fb_bce0
__device__ float g_part[B_ * BLKX * 12];
__device__ unsigned g_cnt = 0;

__device__ __forceinline__ float sl1(float x, float y) {
  float d = x - y, ad = fabsf(d);
  return ad < 1.0f ? 0.5f * d * d : ad - 0.5f;
}
__device__ __forceinline__ int f2ord(float f) {
  int i = __float_as_int(f);
  return i ^ ((i >> 31) & 0x7fffffff);
}
__device__ __forceinline__ float ord2f(int k) {
  return __int_as_float(k ^ ((k >> 31) & 0x7fffffff));
}

__global__ __launch_bounds__(TPB, 3) void det_loss_fused(
    const float* __restrict__ preds, const float* __restrict__ targets,
    float* __restrict__ out) {
  const int b = blockIdx.y;
  const int tid = threadIdx.x, wid = tid >> 5, lane = tid & 31;

  __shared__ float4 tb[M_];     // raw target boxes
  __shared__ float tcl[M_];     // raw target classes
  __shared__ float4 ct[M_];     // compacted PROPER valid target boxes
  __shared__ float2 cmeta[M_];  // .x = area2, .y = __int_as_float(orig idx)
  __shared__ float wacc[NWARP][12];
  __shared__ bool sLast;
  __shared__ float sloss[B_];

  if (tid < M_) {
    const float* t = targets + ((size_t)b * M_ + tid) * 5;
    tb[tid] = make_float4(t[0], t[1], t[2], t[3]);
    tcl[tid] = t[4];
  }
  __syncthreads();  // barrier 1: tb/tcl visible

  // EVERY warp redundantly computes V / VP / cix0 (no solo-warp straggler);
  // warp 0 additionally writes the compacted PROPER-target arrays.
  // (improper targets give inter==0 -> iou==±0: never beat a positive iou;
  //  the all-zero case resolves to the first VALID index.)
  int vcnt = 0, pcnt = 0, fv = M_;
#pragma unroll
  for (int g = 0; g < 4; g++) {
    int m = g * 32 + lane;
    float4 t = tb[m];
    bool val = tcl[m] != -1.0f;
    bool prop = val && (t.z > t.x) && (t.w > t.y);
    unsigned balv = __ballot_sync(FULLMASK, val);
    unsigned balp = __ballot_sync(FULLMASK, prop);
    if (wid == 0 && prop) {
      int pos = pcnt + __popc(balp & ((1u << lane) - 1u));
      ct[pos] = t;
      cmeta[pos] = make_float2((t.z - t.x) * (t.w - t.y), __int_as_float(m));
    }
    vcnt += __popc(balv);
    pcnt += __popc(balp);
    if (fv == M_ && balv) fv = g * 32 + (__ffs(balv) - 1);
  }
  const int V = vcnt, VP = pcnt;
  const int cix0 = (fv == M_) ? 0 : fv;
  __syncthreads();  // barrier 2: ct/cmeta visible

  // persistent accumulators across reps
  float s_all = 0.f, s_b0u = 0.f;
  float n_m = 0.f, s_bb = 0.f, s_nll = 0.f, s_b1 = 0.f;
  float fmx = -INFINITY;
  float fn = 0.f, fbb = 0.f, fnll = 0.f, fb1 = 0.f, fb0 = 0.f;

  const int g4 = lane >> 2, sub = lane & 3;
  const int g8 = lane >> 3, sub8 = lane & 7;

#pragma unroll 1
  for (int rep = 0; rep < REPS; rep++) {
    const int n = blockIdx.x * CHUNK + rep * TPB + tid;
    const float* row = preds + ((size_t)b * N_ + n) * PW;
    float2 v01 = __ldg((const float2*)row);
    float2 v23 = __ldg(((const float2*)row) + 1);
    float pb0 = v01.x, pb1 = v01.y, pb2 = v23.x, pb3 = v23.y;
    // degenerate preds (or VP==0) can only produce iou==±0 -> skip scan
    const bool scanit = (pb2 > pb0) && (pb3 > pb1) && (VP > 0);

    float biou; int bidx;
    if (V > 0) { biou = 0.0f; bidx = cix0; }  // default: all ious ±0
    else       { biou = NEGV; bidx = 0; }     // no valid targets

    // ---- warp-local scan: 4 lanes per pred, 8 preds per iteration.
    {
      unsigned bal = __ballot_sync(FULLMASK, scanit);
      const int cnt = __popc(bal);
      const int r = __popc(bal & ((1u << lane) - 1u));
      for (int base = 0; base < cnt; base += 8) {
        int k = base + g4;
        unsigned src = (k < cnt) ? __fns(bal, 0, k + 1) : 0u;
        float q0 = __shfl_sync(FULLMASK, pb0, src);
        float q1 = __shfl_sync(FULLMASK, pb1, src);
        float q2 = __shfl_sync(FULLMASK, pb2, src);
        float q3 = __shfl_sync(FULLMASK, pb3, src);
        float a1 = (q2 - q0) * (q3 - q1);
        float lb = 0.0f;        // ious are >0 or ±0
        int li = 0x7fffffff;
#pragma unroll 4
        for (int c = sub; c < VP; c += 4) {
          float4 t = ct[c];
          float2 me = cmeta[c];
          float x1 = fmaxf(q0, t.x), y1 = fmaxf(q1, t.y);
          float x2 = fminf(q2, t.z), y2 = fminf(q3, t.w);
          float inter = fmaxf(x2 - x1, 0.0f) * fmaxf(y2 - y1, 0.0f);
          float den = ((a1 + me.x) - inter) + 1e-6f;  // reference add order
          float iou = __fdividef(inter, den);          // >0 iff inter>0
          if (iou > lb) { lb = iou; li = __float_as_int(me.y); }
        }
        // merge the 4 sub-lanes: (iou desc, orig idx asc)
#pragma unroll
        for (int off = 1; off < 4; off <<= 1) {
          float ol = __shfl_xor_sync(FULLMASK, lb, off);
          int oi = __shfl_xor_sync(FULLMASK, li, off);
          if (ol > lb || (ol == lb && oi < li)) { lb = ol; li = oi; }
        }
        bool pos = lb > 0.0f;
        float rl = pos ? lb : 0.0f;           // all-zero row -> +0
        int ri = pos ? li : cix0;             // ... at first valid index
        // scatter back to owner lanes: owner rank rs -> result at lane 4*rs
        int rs = r - base;
        bool mine = scanit && (rs >= 0) && (rs < 8);
        int idx = mine ? (rs << 2) : 0;
        float gl = __shfl_sync(FULLMASK, rl, idx);
        int gi = __shfl_sync(FULLMASK, ri, idx);
        if (mine) { biou = gl; bidx = gi; }
      }
    }

    float conf = __ldg(row + 4);
    float bce0 = -fmaxf(__logf(1.0f - conf), -100.0f);

    bool matched = biou > 0.4f;
    s_all += bce0;
    if (!matched) s_b0u += bce0;

    // per-warp, per-rep max as fallback tie filter
    float fmx_r = ord2f(__reduce_max_sync(FULLMASK, f2ord(biou)));

    float n_m_r = 0.f, s_bb_r = 0.f, s_nll_r = 0.f, s_b1_r = 0.f;
    float fn_r = 0.f, fbb_r = 0.f, fnll_r = 0.f, fb1_r = 0.f, fb0_r = 0.f;

    // ---- warp-local heavy path: 4 rows per iteration, 8 lanes per row.
    {
      bool heavy = (V > 0) && (matched || (biou == fmx_r));
      unsigned hbal = __ballot_sync(FULLMASK, heavy);
      const int hcnt = __popc(hbal);
      const int wbase = blockIdx.x * CHUNK + rep * TPB + wid * 32;
      for (int hb = 0; hb < hcnt; hb += 4) {
        int k = hb + g8;
        bool act = k < hcnt;
        unsigned src = act ? __fns(hbal, 0, k + 1) : 0u;
        float q0 = __shfl_sync(FULLMASK, pb0, src);
        float q1 = __shfl_sync(FULLMASK, pb1, src);
        float q2 = __shfl_sync(FULLMASK, pb2, src);
        float q3 = __shfl_sync(FULLMASK, pb3, src);
        float qc = __shfl_sync(FULLMASK, conf, src);
        float qb0 = __shfl_sync(FULLMASK, bce0, src);
        float qi2 = __shfl_sync(FULLMASK, biou, src);
        int qx = __shfl_sync(FULLMASK, bidx, src);
        const float* hrow =
            preds + ((size_t)b * N_ + (wbase + (int)src)) * PW + 6;
        // sum of exp over 80 logits, no max shift (logits in [0,1))
        float se = 0.0f;
#pragma unroll
        for (int k2 = 0; k2 < 10; k2++)
          se += __expf(__ldg(hrow + sub8 + 8 * k2));
#pragma unroll
        for (int off = 1; off < 8; off <<= 1)
          se += __shfl_xor_sync(FULLMASK, se, off);
        int e = min(max((int)tcl[qx], 0), NLOG - 1);
        float lv = __ldg(hrow + e);  // L1 hit (sector just fetched)
        float nll = __logf(se) - lv;
        float4 g = tb[qx];
        float ga = (g.z - g.x) * (g.w - g.y);
        float w = (ga < 0.01f) ? 1.5f : 1.0f;
        float bbt =
            (sl1(q0, g.x) + sl1(q1, g.y) + sl1(q2, g.z) + sl1(q3, g.w)) * w;
        float bce1 = -fmaxf(__logf(qc), -100.0f);
        if (act && sub8 == 0) {
          if (qi2 > 0.4f) { n_m_r += 1.f; s_bb_r += bbt; s_nll_r += nll; s_b1_r += bce1; }
          if (qi2 == fmx_r) { fn_r += 1.f; fbb_r += bbt; fnll_r += nll; fb1_r += bce1; fb0_r += qb0; }
        }
      }
    }

    // merge rep partials: matched sums add; fallback is max-with-tie-add
    // (fmx comparisons are warp-uniform -> no divergence)
    n_m += n_m_r; s_bb += s_bb_r; s_nll += s_nll_r; s_b1 += s_b1_r;
    if (fmx_r > fmx) {
      fmx = fmx_r; fn = fn_r; fbb = fbb_r; fnll = fnll_r; fb1 = fb1_r; fb0 = fb0_r;
    } else if (fmx_r == fmx) {
      fn += fn_r; fbb += fbb_r; fnll += fnll_r; fb1 += fb1_r; fb0 += fb0_r;
    }
  }

  // s_all/s_b0u are per-lane over all 32 lanes: full tree.
  // heavy partials live on lanes {0,8,16,24}: folded by the off=8,16 steps.
#pragma unroll
  for (int off = 1; off < 8; off <<= 1) {
    s_all += __shfl_xor_sync(FULLMASK, s_all, off);
    s_b0u += __shfl_xor_sync(FULLMASK, s_b0u, off);
  }
#pragma unroll
  for (int off = 8; off < 32; off <<= 1) {
    s_all += __shfl_xor_sync(FULLMASK, s_all, off);
    s_b0u += __shfl_xor_sync(FULLMASK, s_b0u, off);
    n_m  += __shfl_xor_sync(FULLMASK, n_m, off);
    s_bb += __shfl_xor_sync(FULLMASK, s_bb, off);
    s_nll += __shfl_xor_sync(FULLMASK, s_nll, off);
    s_b1 += __shfl_xor_sync(FULLMASK, s_b1, off);
    fn  += __shfl_xor_sync(FULLMASK, fn, off);
    fbb += __shfl_xor_sync(FULLMASK, fbb, off);
    fnll += __shfl_xor_sync(FULLMASK, fnll, off);
    fb1 += __shfl_xor_sync(FULLMASK, fb1, off);
    fb0 += __shfl_xor_sync(FULLMASK, fb0, off);
  }

  if (lane == 0) {
    float* a = wacc[wid];
    a[0] = n_m; a[1] = s_bb; a[2] = s_nll; a[3] = s_b1; a[4] = s_b0u; a[5] = s_all;
    a[6] = fmx; a[7] = fn; a[8] = fbb; a[9] = fnll; a[10] = fb1; a[11] = fb0;
  }
  __syncthreads();  // barrier 3: wacc visible

  // warp 0: lane-parallel merge of the 16 warp partials (xor tree on 0..15)
  if (wid == 0) {
    float o[12];
    bool has = lane < NWARP;
#pragma unroll
    for (int k = 0; k < 12; k++) o[k] = wacc[has ? lane : 0][k];
    if (!has) {
      o[0] = o[1] = o[2] = o[3] = o[4] = o[5] = 0.f;
      o[6] = -INFINITY; o[7] = o[8] = o[9] = o[10] = o[11] = 0.f;
    }
#pragma unroll
    for (int off = 8; off; off >>= 1) {
      float t[12];
#pragma unroll
      for (int k = 0; k < 12; k++) t[k] = __shfl_xor_sync(FULLMASK, o[k], off);
#pragma unroll
      for (int k = 0; k < 6; k++) o[k] += t[k];
      if (t[6] > o[6]) {
#pragma unroll
        for (int k = 6; k < 12; k++) o[k] = t[k];
      } else if (t[6] == o[6]) {
#pragma unroll
        for (int k = 7; k < 12; k++) o[k] += t[k];
      }
    }
    if (lane == 0) {
      float* g = g_part + ((size_t)b * BLKX + blockIdx.x) * 12;
#pragma unroll
      for (int k = 0; k < 12; k++) g[k] = o[k];
    }
  }

  // ---- fused finalization: last block merges all partials ----
  if (tid == 0) {
    __threadfence();
    unsigned prev = atomicAdd(&g_cnt, 1u);
    sLast = (prev == (unsigned)(gridDim.x * gridDim.y) - 1u);
  }
  __syncthreads();
  if (!sLast) return;
  if (tid == 0) { g_cnt = 0; __threadfence(); }

  for (int bb = wid; bb < B_; bb += NWARP) {
    bool av = false;
#pragma unroll
    for (int k = 0; k < 4; k++)
      av |= (targets[((size_t)bb * M_ + lane * 4 + k) * 5 + 4] != -1.0f);
    bool anyv = __ballot_sync(FULLMASK, av) != 0;

    // lane = chunk (BLKX=16); identity on lanes >= BLKX; xor tree merge
    float o[12];
    bool hasc = lane < BLKX;
    const float* gp = g_part + ((size_t)bb * BLKX + (hasc ? lane : 0)) * 12;
#pragma unroll
    for (int k = 0; k < 12; k++) o[k] = gp[k];
    if (!hasc) {
      o[0] = o[1] = o[2] = o[3] = o[4] = o[5] = 0.f;
      o[6] = -INFINITY; o[7] = o[8] = o[9] = o[10] = o[11] = 0.f;
    }
#pragma unroll
    for (int off = 8; off; off >>= 1) {
      float t[12];
#pragma unroll
      for (int k = 0; k < 12; k++) t[k] = __shfl_xor_sync(FULLMASK, o[k], off);
#pragma unroll
      for (int k = 0; k < 6; k++) o[k] += t[k];
      if (t[6] > o[6]) {
#pragma unroll
        for (int k = 6; k < 12; k++) o[k] = t[k];
      } else if (t[6] == o[6]) {
#pragma unroll
        for (int k = 7; k < 12; k++) o[k] += t[k];
      }
    }

    if (lane == 0) {
      float loss;
      if (!anyv) {
        loss = o[5] / (float)N_;
      } else {
        float n_m2 = o[0], s_bb2 = o[1], s_nll2 = o[2], s_b12 = o[3], s_b0u2 = o[4];
        if (n_m2 == 0.0f) {  // fallback: matched = (best_iou == global max)
          n_m2 = o[7]; s_bb2 = o[8]; s_nll2 = o[9]; s_b12 = o[10];
          s_b0u2 = o[5] - o[11];
        }
        float ns = fmaxf(n_m2, 1.0f);
        float bbox = s_bb2 / (ns * 4.0f);
        float cls = s_nll2 / ns;
        float m_conf = s_b12 / ns;
        float n_u = (float)N_ - n_m2;
        float u_conf = s_b0u2 / fmaxf(n_u, 1.0f);
        float conf_loss = (n_u > 0.0f) ? (m_conf + u_conf) * 0.5f : m_conf;
        loss = bbox * 5.0f + cls + conf_loss * 2.0f;
      }
      sloss[bb] = loss;
    }
  }
  __syncthreads();
  if (tid < 32) {
    float v = sloss[tid];
#pragma unroll
    for (int off = 16; off; off >>= 1) v += __shfl_xor_sync(FULLMASK, v, off);
    if (tid == 0) *out = v / (float)B_;
  }
}

extern "C" void kernel_launch(void* const* d_in, const int* in_sizes, int n_in,
                              void* d_out, int out_size) {
  const float* preds = (const float*)d_in[0];
  const float* targets = (const float*)d_in[1];
  float* out = (float*)d_out;
  dim3 grid(BLKX, B_);
  det_loss_fused<<<grid, TPB>>>(preds, targets, out);
}

// round 15
// speedup vs baseline: 1.0730x; 1.0730x over previous
#include <cuda_runtime.h>
#include <math.h>

#define FULLMASK 0xffffffffu
constexpr int B_ = 32, N_ = 16384, M_ = 128, PW = 86, NLOG = 80;
constexpr int TPB = 512, BLKX = N_ / TPB;  // 32 chunks per image
constexpr int NWARP = TPB / 32;            // 16
constexpr float NEGV = -1000000000.0f;

// per-(image,chunk) partials:
// [0]=n_m [1]=s_bbox [2]=s_nll [3]=s_bce1 [4]=s_bce0_unmatched [5]=s_bce0_all
// [6]=fb_max [7]=fb_n [8]=fb_bbox [9]=fb_nll [10]=fb_bce1 [11]=fb_bce0
__device__ float g_part[B_ * BLKX * 12];
__device__ unsigned g_cnt = 0;

__device__ __forceinline__ float sl1(float x, float y) {
  float d = x - y, ad = fabsf(d);
  return ad < 1.0f ? 0.5f * d * d : ad - 0.5f;
}
__device__ __forceinline__ int f2ord(float f) {
  int i = __float_as_int(f);
  return i ^ ((i >> 31) & 0x7fffffff);
}
__device__ __forceinline__ float ord2f(int k) {
  return __int_as_float(k ^ ((k >> 31) & 0x7fffffff));
}

__global__ __launch_bounds__(TPB, 3) void det_loss_fused(
    const float* __restrict__ preds, const float* __restrict__ targets,
    float* __restrict__ out) {
  const int b = blockIdx.y;
  const int tid = threadIdx.x, wid = tid >> 5, lane = tid & 31;

  __shared__ float4 tb[M_];     // raw target boxes
  __shared__ float tcl[M_];     // raw target classes
  __shared__ float4 ct[M_];     // compacted PROPER valid target boxes
  __shared__ float2 cmeta[M_];  // .x = area2, .y = __int_as_float(orig idx)
  __shared__ int sQ, sHQ;
  __shared__ float4 qbox[TPB];  // scan queue boxes; later: per-tid boxes
  __shared__ short qown[TPB];
  __shared__ float riou[TPB];   // per-tid best iou
  __shared__ short ridx[TPB];   // per-tid best idx
  __shared__ float sconf[TPB];
  __shared__ float sbce0[TPB];
  __shared__ short hq[TPB];     // heavy queue (tids)
  __shared__ float swmax[NWARP];
  __shared__ float wacc[NWARP][12];
  __shared__ bool sLast;
  __shared__ float sloss[B_];

  // issue pred box load first: overlaps targets fill + compaction latency
  const int n = blockIdx.x * TPB + tid;
  const float* row = preds + ((size_t)b * N_ + n) * PW;
  float2 v01 = __ldg((const float2*)row);
  float2 v23 = __ldg(((const float2*)row) + 1);

  if (tid == 0) { sQ = 0; sHQ = 0; }
  if (tid < M_) {
    const float* t = targets + ((size_t)b * M_ + tid) * 5;
    tb[tid] = make_float4(t[0], t[1], t[2], t[3]);
    tcl[tid] = t[4];
  }
  __syncthreads();  // barrier 1: tb/tcl, sQ/sHQ visible

  // EVERY warp redundantly computes V / VP / cix0 (no solo-warp straggler);
  // warp 0 additionally writes the compacted PROPER-target arrays.
  // (improper targets give inter==0 -> iou==±0: never beat a positive iou;
  //  the all-zero case resolves to the first VALID index.)
  int vcnt = 0, pcnt = 0, fv = M_;
#pragma unroll
  for (int g = 0; g < 4; g++) {
    int m = g * 32 + lane;
    float4 t = tb[m];
    bool val = tcl[m] != -1.0f;
    bool prop = val && (t.z > t.x) && (t.w > t.y);
    unsigned balv = __ballot_sync(FULLMASK, val);
    unsigned balp = __ballot_sync(FULLMASK, prop);
    if (wid == 0 && prop) {
      int pos = pcnt + __popc(balp & ((1u << lane) - 1u));
      ct[pos] = t;
      cmeta[pos] = make_float2((t.z - t.x) * (t.w - t.y), __int_as_float(m));
    }
    vcnt += __popc(balv);
    pcnt += __popc(balp);
    if (fv == M_ && balv) fv = g * 32 + (__ffs(balv) - 1);
  }
  const int V = vcnt, VP = pcnt;
  const int cix0 = (fv == M_) ? 0 : fv;
  // NO barrier here: the queue barrier below also orders warp 0's ct/cmeta
  // writes against all scan-phase reads.

  float pb0 = v01.x, pb1 = v01.y, pb2 = v23.x, pb3 = v23.y;
  // degenerate preds (or VP==0) can only produce iou==±0 -> skip scan
  const bool scanit = (pb2 > pb0) && (pb3 > pb1) && (VP > 0);

  // enqueue preds needing a scan (slot order irrelevant; keyed by owner tid)
  {
    unsigned bal = __ballot_sync(FULLMASK, scanit);
    int cnt = __popc(bal);
    int qb = 0;
    if (lane == 0 && cnt) qb = atomicAdd(&sQ, cnt);
    qb = __shfl_sync(FULLMASK, qb, 0);
    if (scanit) {
      int pos = qb + __popc(bal & ((1u << lane) - 1u));
      qbox[pos] = make_float4(pb0, pb1, pb2, pb3);
      qown[pos] = (short)tid;
    }
  }
  __syncthreads();  // barrier 2: ct/cmeta + qbox/qown/sQ visible
  const int Q = sQ;

  // ---- balanced scan over PROPER targets: 4 lanes/pred, 8 preds/warp/iter.
  // Loop bound depends only on (wid, Q): warp-uniform -> collectives safe.
  const int sub = tid & 3;
  for (int qb2 = wid * 8; qb2 < Q; qb2 += NWARP * 8) {
    int qi = qb2 + (lane >> 2);
    bool act = qi < Q;
    int qis = act ? qi : (Q - 1);  // Q>=1 inside loop
    float4 p = qbox[qis];
    float a1 = (p.z - p.x) * (p.w - p.y);
    float lb = 0.0f;        // ious are >0 or ±0; 0 = "no positive found"
    int li = 0x7fffffff;
#pragma unroll 4
    for (int c = sub; c < VP; c += 4) {
      float4 t = ct[c];
      float2 me = cmeta[c];
      float x1 = fmaxf(p.x, t.x), y1 = fmaxf(p.y, t.y);
      float x2 = fminf(p.z, t.z), y2 = fminf(p.w, t.w);
      float inter = fmaxf(x2 - x1, 0.0f) * fmaxf(y2 - y1, 0.0f);
      float den = ((a1 + me.x) - inter) + 1e-6f;  // reference add order
      float iou = __fdividef(inter, den);          // >0 iff inter>0
      if (iou > lb) { lb = iou; li = __float_as_int(me.y); }
    }
    // merge the 4 sub-lanes: (iou desc, orig idx asc); all lanes participate
#pragma unroll
    for (int off = 1; off < 4; off <<= 1) {
      float ol = __shfl_xor_sync(FULLMASK, lb, off);
      int oi = __shfl_xor_sync(FULLMASK, li, off);
      if (ol > lb || (ol == lb && oi < li)) { lb = ol; li = oi; }
    }
    if (act && sub == 0) {
      int ow = qown[qi];
      bool pos = lb > 0.0f;
      riou[ow] = pos ? lb : 0.0f;           // all-zero row -> +0
      ridx[ow] = (short)(pos ? li : cix0);  // ... at first valid index
    }
  }
  __syncthreads();  // barrier 3: scan results visible

  float biou; int bidx;
  if (scanit)      { biou = riou[tid]; bidx = ridx[tid]; }
  else if (V > 0)  { biou = 0.0f; bidx = cix0; }  // all ious ±0
  else             { biou = NEGV; bidx = 0; }     // no valid targets

  // conf loaded here (after scan) to shorten live range
  float conf = __ldg(row + 4);
  float bce0 = -fmaxf(__logf(1.0f - conf), -100.0f);

  bool matched = biou > 0.4f;
  float s_all = bce0;
  float s_b0u = matched ? 0.0f : bce0;
  // reduce per-lane sums across warp now (uniform flow)
#pragma unroll
  for (int off = 16; off; off >>= 1) {
    s_all += __shfl_xor_sync(FULLMASK, s_all, off);
    s_b0u += __shfl_xor_sync(FULLMASK, s_b0u, off);
  }

  // block-wide max of biou -> fallback tie filter
  {
    float wm = ord2f(__reduce_max_sync(FULLMASK, f2ord(biou)));
    if (lane == 0) swmax[wid] = wm;
  }
  __syncthreads();  // barrier 4: swmax visible
  float fmx = swmax[0];
#pragma unroll
  for (int k = 1; k < NWARP; k++) fmx = fmaxf(fmx, swmax[k]);

  // park per-tid state; enqueue heavy preds (matched or tie) into hq
  qbox[tid] = make_float4(pb0, pb1, pb2, pb3);  // scan done; safe to overwrite
  sconf[tid] = conf;
  sbce0[tid] = bce0;
  riou[tid] = biou;
  ridx[tid] = (short)bidx;
  {
    bool heavy = (V > 0) && (matched || (biou == fmx));
    unsigned bal = __ballot_sync(FULLMASK, heavy);
    int cnt = __popc(bal);
    int qb = 0;
    if (lane == 0 && cnt) qb = atomicAdd(&sHQ, cnt);
    qb = __shfl_sync(FULLMASK, qb, 0);
    if (heavy) {
      int pos = qb + __popc(bal & ((1u << lane) - 1u));
      hq[pos] = (short)tid;
    }
  }
  __syncthreads();  // barrier 5: parked state + hq visible
  const int HQ = sHQ;

  float n_m = 0.f, s_bb = 0.f, s_nll = 0.f, s_b1 = 0.f;
  float fn = 0.f, fbb = 0.f, fnll = 0.f, fb1 = 0.f, fb0 = 0.f;

  // ---- heavy path: 4 rows per warp round, 8 lanes per row.
  const int sub8 = lane & 7;
  for (int h0 = wid * 4; h0 < HQ; h0 += NWARP * 4) {
    int hi = h0 + (lane >> 3);
    bool act = hi < HQ;
    int t = hq[act ? hi : (HQ - 1)];  // HQ>=1 inside loop
    float4 p = qbox[t];
    float qc = sconf[t];
    float qb0 = sbce0[t];
    float qi2 = riou[t];
    int qx = ridx[t];
    const float* hrow =
        preds + ((size_t)b * N_ + (blockIdx.x * TPB + t)) * PW + 6;
    // sum of exp over 80 logits, no max shift (logits in [0,1): no overflow)
    float se = 0.0f;
#pragma unroll
    for (int k = 0; k < 10; k++) se += __expf(__ldg(hrow + sub8 + 8 * k));
#pragma unroll
    for (int off = 1; off < 8; off <<= 1)
      se += __shfl_xor_sync(FULLMASK, se, off);
    int e = min(max((int)tcl[qx], 0), NLOG - 1);
    float lv = __ldg(hrow + e);  // L1 hit (sector just fetched)
    float nll = __logf(se) - lv;
    float4 g = tb[qx];
    float ga = (g.z - g.x) * (g.w - g.y);
    float w = (ga < 0.01f) ? 1.5f : 1.0f;
    float bbt = (sl1(p.x, g.x) + sl1(p.y, g.y) + sl1(p.z, g.z) + sl1(p.w, g.w)) * w;
    float bce1 = -fmaxf(__logf(qc), -100.0f);
    if (act && sub8 == 0) {
      if (qi2 > 0.4f) { n_m += 1.f; s_bb += bbt; s_nll += nll; s_b1 += bce1; }
      if (qi2 == fmx) { fn += 1.f; fbb += bbt; fnll += nll; fb1 += bce1; fb0 += qb0; }
    }
  }

  // partials live only on lanes {0,8,16,24}: 2 xor steps suffice
#pragma unroll
  for (int off = 8; off < 32; off <<= 1) {
    n_m  += __shfl_xor_sync(FULLMASK, n_m, off);
    s_bb += __shfl_xor_sync(FULLMASK, s_bb, off);
    s_nll += __shfl_xor_sync(FULLMASK, s_nll, off);
    s_b1 += __shfl_xor_sync(FULLMASK, s_b1, off);
    fn  += __shfl_xor_sync(FULLMASK, fn, off);
    fbb += __shfl_xor_sync(FULLMASK, fbb, off);
    fnll += __shfl_xor_sync(FULLMASK, fnll, off);
    fb1 += __shfl_xor_sync(FULLMASK, fb1, off);
    fb0 += __shfl_xor_sync(FULLMASK, fb0, off);
  }

  if (lane == 0) {
    float* a = wacc[wid];
    a[0] = n_m; a[1] = s_bb; a[2] = s_nll; a[3] = s_b1; a[4] = s_b0u; a[5] = s_all;
    a[6] = fmx; a[7] = fn; a[8] = fbb; a[9] = fnll; a[10] = fb1; a[11] = fb0;
  }
  __syncthreads();  // barrier 6: wacc visible

  // warp 0: lane-parallel merge of the 16 warp partials (xor tree on 0..15)
  if (wid == 0) {
    float o[12];
    bool has = lane < NWARP;
#pragma unroll
    for (int k = 0; k < 12; k++) o[k] = wacc[has ? lane : 0][k];
    if (!has) {
      o[0] = o[1] = o[2] = o[3] = o[4] = o[5] = 0.f;
      o[6] = -INFINITY; o[7] = o[8] = o[9] = o[10] = o[11] = 0.f;
    }
#pragma unroll
    for (int off = 8; off; off >>= 1) {
      float t[12];
#pragma unroll
      for (int k = 0; k < 12; k++) t[k] = __shfl_xor_sync(FULLMASK, o[k], off);
#pragma unroll
      for (int k = 0; k < 6; k++) o[k] += t[k];
      if (t[6] > o[6]) {
#pragma unroll
        for (int k = 6; k < 12; k++) o[k] = t[k];
      } else if (t[6] == o[6]) {
#pragma unroll
        for (int k = 7; k < 12; k++) o[k] += t[k];
      }
    }
    if (lane == 0) {
      float* g = g_part + ((size_t)b * BLKX + blockIdx.x) * 12;
#pragma unroll
      for (int k = 0; k < 12; k++) g[k] = o[k];
    }
  }

  // ---- fused finalization: last block merges all partials ----
  if (tid == 0) {
    __threadfence();
    unsigned prev = atomicAdd(&g_cnt, 1u);
    sLast = (prev == (unsigned)(gridDim.x * gridDim.y) - 1u);
  }
  __syncthreads();
  if (!sLast) return;
  if (tid == 0) { g_cnt = 0; __threadfence(); }

  for (int bb = wid; bb < B_; bb += NWARP) {
    bool av = false;
#pragma unroll
    for (int k = 0; k < 4; k++)
      av |= (targets[((size_t)bb * M_ + lane * 4 + k) * 5 + 4] != -1.0f);
    bool anyv = __ballot_sync(FULLMASK, av) != 0;

    // lane = chunk; xor-shuffle tree merge (commutative: max-merge w/ tie-add)
    float o[12];
    const float* gp = g_part + ((size_t)bb * BLKX + lane) * 12;
#pragma unroll
    for (int k = 0; k < 12; k++) o[k] = gp[k];
#pragma unroll
    for (int off = 16; off; off >>= 1) {
      float t[12];
#pragma unroll
      for (int k = 0; k < 12; k++) t[k] = __shfl_xor_sync(FULLMASK, o[k], off);
#pragma unroll
      for (int k = 0; k < 6; k++) o[k] += t[k];
      if (t[6] > o[6]) {
#pragma unroll
        for (int k = 6; k < 12; k++) o[k] = t[k];
      } else if (t[6] == o[6]) {
#pragma unroll
        for (int k = 7; k < 12; k++) o[k] += t[k];
      }
    }

    if (lane == 0) {
      float loss;
      if (!anyv) {
        loss = o[5] / (float)N_;
      } else {
        float n_m2 = o[0], s_bb2 = o[1], s_nll2 = o[2], s_b12 = o[3], s_b0u2 = o[4];
        if (n_m2 == 0.0f) {  // fallback: matched = (best_iou == global max)
          n_m2 = o[7]; s_bb2 = o[8]; s_nll2 = o[9]; s_b12 = o[10];
          s_b0u2 = o[5] - o[11];
        }
        float ns = fmaxf(n_m2, 1.0f);
        float bbox = s_bb2 / (ns * 4.0f);
        float cls = s_nll2 / ns;
        float m_conf = s_b12 / ns;
        float n_u = (float)N_ - n_m2;
        float u_conf = s_b0u2 / fmaxf(n_u, 1.0f);
        float conf_loss = (n_u > 0.0f) ? (m_conf + u_conf) * 0.5f : m_conf;
        loss = bbox * 5.0f + cls + conf_loss * 2.0f;
      }
      sloss[bb] = loss;
    }
  }
  __syncthreads();
  if (tid < 32) {
    float v = sloss[tid];
#pragma unroll
    for (int off = 16; off; off >>= 1) v += __shfl_xor_sync(FULLMASK, v, off);
    if (tid == 0) *out = v / (float)B_;
  }
}

extern "C" void kernel_launch(void* const* d_in, const int* in_sizes, int n_in,
                              void* d_out, int out_size) {
  const float* preds = (const float*)d_in[0];
  const float* targets = (const float*)d_in[1];
  float* out = (float*)d_out;
  dim3 grid(BLKX, B_);
  det_loss_fused<<<grid, TPB>>>(preds, targets, out);
}

// round 16
// speedup vs baseline: 1.1023x; 1.0274x over previous
#include <cuda_runtime.h>
#include <math.h>

#define FULLMASK 0xffffffffu
constexpr int B_ = 32, N_ = 16384, M_ = 128, PW = 86, NLOG = 80;
constexpr int TPB = 512, BLKX = N_ / TPB;  // 32 chunks per image
constexpr int NWARP = TPB / 32;            // 16
constexpr float NEGV = -1000000000.0f;

// per-(image,chunk) partials:
// [0]=n_m [1]=s_bbox [2]=s_nll [3]=s_bce1 [4]=s_bce0_unmatched [5]=s_bce0_all
// [6]=fb_max [7]=fb_n [8]=fb_bbox [9]=fb_nll [10]=fb_bce1 [11]=fb_bce0
__device__ float g_part[B_ * BLKX * 12];
__device__ unsigned g_cnt = 0;

__device__ __forceinline__ float sl1(float x, float y) {
  float d = x - y, ad = fabsf(d);
  return ad < 1.0f ? 0.5f * d * d : ad - 0.5f;
}
__device__ __forceinline__ int f2ord(float f) {
  int i = __float_as_int(f);
  return i ^ ((i >> 31) & 0x7fffffff);
}
__device__ __forceinline__ float ord2f(int k) {
  return __int_as_float(k ^ ((k >> 31) & 0x7fffffff));
}

__global__ __launch_bounds__(TPB, 3) void det_loss_fused(
    const float* __restrict__ preds, const float* __restrict__ targets,
    float* __restrict__ out) {
  const int b = blockIdx.y;
  const int tid = threadIdx.x, wid = tid >> 5, lane = tid & 31;

  __shared__ float4 tb[M_];     // raw target boxes
  __shared__ float tcl[M_];     // raw target classes
  __shared__ float4 ct[M_];     // compacted PROPER valid target boxes
  __shared__ float2 cmeta[M_];  // .x = area2, .y = __int_as_float(orig idx)
  __shared__ int sQ, sHQ;
  __shared__ float4 qbox[TPB];  // scan queue boxes; later: per-tid boxes
  __shared__ short qown[TPB];
  __shared__ float riou[TPB];   // per-tid best iou
  __shared__ short ridx[TPB];   // per-tid best idx
  __shared__ float sconf[TPB];
  __shared__ float sbce0[TPB];
  __shared__ short hq[TPB];     // heavy queue (tids)
  __shared__ float swmax[NWARP];
  __shared__ float wacc[NWARP][12];
  __shared__ bool sLast;
  __shared__ float sloss[B_];

  // issue pred box load first: overlaps targets fill + compaction latency
  const int n = blockIdx.x * TPB + tid;
  const float* row = preds + ((size_t)b * N_ + n) * PW;
  float2 v01 = __ldg((const float2*)row);
  float2 v23 = __ldg(((const float2*)row) + 1);

  if (tid == 0) { sQ = 0; sHQ = 0; }
  if (tid < M_) {
    const float* t = targets + ((size_t)b * M_ + tid) * 5;
    tb[tid] = make_float4(t[0], t[1], t[2], t[3]);
    tcl[tid] = t[4];
  }
  __syncthreads();  // barrier 1: tb/tcl, sQ/sHQ visible

  // EVERY warp redundantly computes V / VP / cix0 (no solo-warp straggler);
  // warp 0 additionally writes the compacted PROPER-target arrays.
  // (improper targets give inter==0 -> iou==±0: never beat a positive iou;
  //  the all-zero case resolves to the first VALID index.)
  int vcnt = 0, pcnt = 0, fv = M_;
#pragma unroll
  for (int g = 0; g < 4; g++) {
    int m = g * 32 + lane;
    float4 t = tb[m];
    bool val = tcl[m] != -1.0f;
    bool prop = val && (t.z > t.x) && (t.w > t.y);
    unsigned balv = __ballot_sync(FULLMASK, val);
    unsigned balp = __ballot_sync(FULLMASK, prop);
    if (wid == 0 && prop) {
      int pos = pcnt + __popc(balp & ((1u << lane) - 1u));
      ct[pos] = t;
      cmeta[pos] = make_float2((t.z - t.x) * (t.w - t.y), __int_as_float(m));
    }
    vcnt += __popc(balv);
    pcnt += __popc(balp);
    if (fv == M_ && balv) fv = g * 32 + (__ffs(balv) - 1);
  }
  const int V = vcnt, VP = pcnt;
  const int cix0 = (fv == M_) ? 0 : fv;
  // NO barrier here: the queue barrier below also orders warp 0's ct/cmeta
  // writes against all scan-phase reads.

  float pb0 = v01.x, pb1 = v01.y, pb2 = v23.x, pb3 = v23.y;
  // degenerate preds (or VP==0) can only produce iou==±0 -> skip scan
  const bool scanit = (pb2 > pb0) && (pb3 > pb1) && (VP > 0);

  // enqueue preds needing a scan (slot order irrelevant; keyed by owner tid)
  {
    unsigned bal = __ballot_sync(FULLMASK, scanit);
    int cnt = __popc(bal);
    int qb = 0;
    if (lane == 0 && cnt) qb = atomicAdd(&sQ, cnt);
    qb = __shfl_sync(FULLMASK, qb, 0);
    if (scanit) {
      int pos = qb + __popc(bal & ((1u << lane) - 1u));
      qbox[pos] = make_float4(pb0, pb1, pb2, pb3);
      qown[pos] = (short)tid;
    }
  }
  __syncthreads();  // barrier 2: ct/cmeta + qbox/qown/sQ visible
  const int Q = sQ;

  // ---- balanced scan over PROPER targets: 4 lanes/pred, 8 preds/warp/iter.
  // Loop bound depends only on (wid, Q): warp-uniform -> collectives safe.
  const int sub = tid & 3;
  for (int qb2 = wid * 8; qb2 < Q; qb2 += NWARP * 8) {
    int qi = qb2 + (lane >> 2);
    bool act = qi < Q;
    int qis = act ? qi : (Q - 1);  // Q>=1 inside loop
    float4 p = qbox[qis];
    float a1 = (p.z - p.x) * (p.w - p.y);
    float lb = 0.0f;        // ious are >0 or ±0; 0 = "no positive found"
    int li = 0x7fffffff;
#pragma unroll 4
    for (int c = sub; c < VP; c += 4) {
      float4 t = ct[c];
      float2 me = cmeta[c];
      float x1 = fmaxf(p.x, t.x), y1 = fmaxf(p.y, t.y);
      float x2 = fminf(p.z, t.z), y2 = fminf(p.w, t.w);
      float inter = fmaxf(x2 - x1, 0.0f) * fmaxf(y2 - y1, 0.0f);
      float den = ((a1 + me.x) - inter) + 1e-6f;  // reference add order
      float iou = __fdividef(inter, den);          // >0 iff inter>0
      if (iou > lb) { lb = iou; li = __float_as_int(me.y); }
    }
    // merge the 4 sub-lanes: (iou desc, orig idx asc); all lanes participate
#pragma unroll
    for (int off = 1; off < 4; off <<= 1) {
      float ol = __shfl_xor_sync(FULLMASK, lb, off);
      int oi = __shfl_xor_sync(FULLMASK, li, off);
      if (ol > lb || (ol == lb && oi < li)) { lb = ol; li = oi; }
    }
    if (act && sub == 0) {
      int ow = qown[qi];
      bool pos = lb > 0.0f;
      riou[ow] = pos ? lb : 0.0f;           // all-zero row -> +0
      ridx[ow] = (short)(pos ? li : cix0);  // ... at first valid index
    }
  }
  __syncthreads();  // barrier 3: scan results visible

  float biou; int bidx;
  if (scanit)      { biou = riou[tid]; bidx = ridx[tid]; }
  else if (V > 0)  { biou = 0.0f; bidx = cix0; }  // all ious ±0
  else             { biou = NEGV; bidx = 0; }     // no valid targets

  // conf loaded here (after scan) to shorten live range
  float conf = __ldg(row + 4);
  float bce0 = -fmaxf(__logf(1.0f - conf), -100.0f);

  bool matched = biou > 0.4f;
  float s_all = bce0;
  float s_b0u = matched ? 0.0f : bce0;
  // partial reduce (off=1..4); final off=8,16 folded into the shared tree
#pragma unroll
  for (int off = 1; off < 8; off <<= 1) {
    s_all += __shfl_xor_sync(FULLMASK, s_all, off);
    s_b0u += __shfl_xor_sync(FULLMASK, s_b0u, off);
  }

  // warp-level max of biou: published for block max; also a SUPERSET filter
  // for heavy enqueue (warp-max ties contain all block-max ties; non-block
  // ties contribute nothing in the heavy loop's conditions).
  float fmx_w = ord2f(__reduce_max_sync(FULLMASK, f2ord(biou)));
  if (lane == 0) swmax[wid] = fmx_w;

  // park per-tid state; enqueue heavy preds (matched or warp-tie) into hq
  qbox[tid] = make_float4(pb0, pb1, pb2, pb3);  // scan done; safe to overwrite
  sconf[tid] = conf;
  sbce0[tid] = bce0;
  riou[tid] = biou;
  ridx[tid] = (short)bidx;
  {
    bool heavy = (V > 0) && (matched || (biou == fmx_w));
    unsigned bal = __ballot_sync(FULLMASK, heavy);
    int cnt = __popc(bal);
    int qb = 0;
    if (lane == 0 && cnt) qb = atomicAdd(&sHQ, cnt);
    qb = __shfl_sync(FULLMASK, qb, 0);
    if (heavy) {
      int pos = qb + __popc(bal & ((1u << lane) - 1u));
      hq[pos] = (short)tid;
    }
  }
  __syncthreads();  // barrier 4: swmax + parked state + hq visible
  const int HQ = sHQ;

  // block-wide max (accumulation conditions key off this, exactly as before)
  float fmx = swmax[0];
#pragma unroll
  for (int k = 1; k < NWARP; k++) fmx = fmaxf(fmx, swmax[k]);

  float n_m = 0.f, s_bb = 0.f, s_nll = 0.f, s_b1 = 0.f;
  float fn = 0.f, fbb = 0.f, fnll = 0.f, fb1 = 0.f, fb0 = 0.f;

  // ---- heavy path: 4 rows per warp round, 8 lanes per row.
  const int sub8 = lane & 7;
  for (int h0 = wid * 4; h0 < HQ; h0 += NWARP * 4) {
    int hi = h0 + (lane >> 3);
    bool act = hi < HQ;
    int t = hq[act ? hi : (HQ - 1)];  // HQ>=1 inside loop
    float4 p = qbox[t];
    float qc = sconf[t];
    float qb0 = sbce0[t];
    float qi2 = riou[t];
    int qx = ridx[t];
    const float* hrow =
        preds + ((size_t)b * N_ + (blockIdx.x * TPB + t)) * PW + 6;
    // sum of exp over 80 logits, no max shift (logits in [0,1): no overflow)
    float se = 0.0f;
#pragma unroll
    for (int k = 0; k < 10; k++) se += __expf(__ldg(hrow + sub8 + 8 * k));
#pragma unroll
    for (int off = 1; off < 8; off <<= 1)
      se += __shfl_xor_sync(FULLMASK, se, off);
    int e = min(max((int)tcl[qx], 0), NLOG - 1);
    float lv = __ldg(hrow + e);  // L1 hit (sector just fetched)
    float nll = __logf(se) - lv;
    float4 g = tb[qx];
    float ga = (g.z - g.x) * (g.w - g.y);
    float w = (ga < 0.01f) ? 1.5f : 1.0f;
    float bbt = (sl1(p.x, g.x) + sl1(p.y, g.y) + sl1(p.z, g.z) + sl1(p.w, g.w)) * w;
    float bce1 = -fmaxf(__logf(qc), -100.0f);
    if (act && sub8 == 0) {
      if (qi2 > 0.4f) { n_m += 1.f; s_bb += bbt; s_nll += nll; s_b1 += bce1; }
      if (qi2 == fmx) { fn += 1.f; fbb += bbt; fnll += nll; fb1 += bce1; fb0 += qb0; }
    }
  }

  // heavy partials live on lanes {0,8,16,24}; s_all/s_b0u already reduced
  // within 8-lane groups: the off=8,16 steps finish both.
#pragma unroll
  for (int off = 8; off < 32; off <<= 1) {
    s_all += __shfl_xor_sync(FULLMASK, s_all, off);
    s_b0u += __shfl_xor_sync(FULLMASK, s_b0u, off);
    n_m  += __shfl_xor_sync(FULLMASK, n_m, off);
    s_bb += __shfl_xor_sync(FULLMASK, s_bb, off);
    s_nll += __shfl_xor_sync(FULLMASK, s_nll, off);
    s_b1 += __shfl_xor_sync(FULLMASK, s_b1, off);
    fn  += __shfl_xor_sync(FULLMASK, fn, off);
    fbb += __shfl_xor_sync(FULLMASK, fbb, off);
    fnll += __shfl_xor_sync(FULLMASK, fnll, off);
    fb1 += __shfl_xor_sync(FULLMASK, fb1, off);
    fb0 += __shfl_xor_sync(FULLMASK, fb0, off);
  }

  if (lane == 0) {
    float* a = wacc[wid];
    a[0] = n_m; a[1] = s_bb; a[2] = s_nll; a[3] = s_b1; a[4] = s_b0u; a[5] = s_all;
    a[6] = fmx; a[7] = fn; a[8] = fbb; a[9] = fnll; a[10] = fb1; a[11] = fb0;
  }
  __syncthreads();  // barrier 5: wacc visible

  // warp 0: lane-parallel merge of the 16 warp partials (xor tree on 0..15)
  if (wid == 0) {
    float o[12];
    bool has = lane < NWARP;
#pragma unroll
    for (int k = 0; k < 12; k++) o[k] = wacc[has ? lane : 0][k];
    if (!has) {
      o[0] = o[1] = o[2] = o[3] = o[4] = o[5] = 0.f;
      o[6] = -INFINITY; o[7] = o[8] = o[9] = o[10] = o[11] = 0.f;
    }
#pragma unroll
    for (int off = 8; off; off >>= 1) {
      float t[12];
#pragma unroll
      for (int k = 0; k < 12; k++) t[k] = __shfl_xor_sync(FULLMASK, o[k], off);
#pragma unroll
      for (int k = 0; k < 6; k++) o[k] += t[k];
      if (t[6] > o[6]) {
#pragma unroll
        for (int k = 6; k < 12; k++) o[k] = t[k];
      } else if (t[6] == o[6]) {
#pragma unroll
        for (int k = 7; k < 12; k++) o[k] += t[k];
      }
    }
    if (lane == 0) {
      float* g = g_part + ((size_t)b * BLKX + blockIdx.x) * 12;
#pragma unroll
      for (int k = 0; k < 12; k++) g[k] = o[k];
    }
  }

  // ---- fused finalization: last block merges all partials ----
  if (tid == 0) {
    __threadfence();
    unsigned prev = atomicAdd(&g_cnt, 1u);
    sLast = (prev == (unsigned)(gridDim.x * gridDim.y) - 1u);
  }
  __syncthreads();
  if (!sLast) return;
  if (tid == 0) { g_cnt = 0; __threadfence(); }

  for (int bb = wid; bb < B_; bb += NWARP) {
    bool av = false;
#pragma unroll
    for (int k = 0; k < 4; k++)
      av |= (targets[((size_t)bb * M_ + lane * 4 + k) * 5 + 4] != -1.0f);
    bool anyv = __ballot_sync(FULLMASK, av) != 0;

    // lane = chunk; xor-shuffle tree merge (commutative: max-merge w/ tie-add)
    float o[12];
    const float* gp = g_part + ((size_t)bb * BLKX + lane) * 12;
#pragma unroll
    for (int k = 0; k < 12; k++) o[k] = gp[k];
#pragma unroll
    for (int off = 16; off; off >>= 1) {
      float t[12];
#pragma unroll
      for (int k = 0; k < 12; k++) t[k] = __shfl_xor_sync(FULLMASK, o[k], off);
#pragma unroll
      for (int k = 0; k < 6; k++) o[k] += t[k];
      if (t[6] > o[6]) {
#pragma unroll
        for (int k = 6; k < 12; k++) o[k] = t[k];
      } else if (t[6] == o[6]) {
#pragma unroll
        for (int k = 7; k < 12; k++) o[k] += t[k];
      }
    }

    if (lane == 0) {
      float loss;
      if (!anyv) {
        loss = o[5] / (float)N_;
      } else {
        float n_m2 = o[0], s_bb2 = o[1], s_nll2 = o[2], s_b12 = o[3], s_b0u2 = o[4];
        if (n_m2 == 0.0f) {  // fallback: matched = (best_iou == global max)
          n_m2 = o[7]; s_bb2 = o[8]; s_nll2 = o[9]; s_b12 = o[10];
          s_b0u2 = o[5] - o[11];
        }
        float ns = fmaxf(n_m2, 1.0f);
        float bbox = s_bb2 / (ns * 4.0f);
        float cls = s_nll2 / ns;
        float m_conf = s_b12 / ns;
        float n_u = (float)N_ - n_m2;
        float u_conf = s_b0u2 / fmaxf(n_u, 1.0f);
        float conf_loss = (n_u > 0.0f) ? (m_conf + u_conf) * 0.5f : m_conf;
        loss = bbox * 5.0f + cls + conf_loss * 2.0f;
      }
      sloss[bb] = loss;
    }
  }
  __syncthreads();
  if (tid < 32) {
    float v = sloss[tid];
#pragma unroll
    for (int off = 16; off; off >>= 1) v += __shfl_xor_sync(FULLMASK, v, off);
    if (tid == 0) *out = v / (float)B_;
  }
}

extern "C" void kernel_launch(void* const* d_in, const int* in_sizes, int n_in,
                              void* d_out, int out_size) {
  const float* preds = (const float*)d_in[0];
  const float* targets = (const float*)d_in[1];
  float* out = (float*)d_out;
  dim3 grid(BLKX, B_);
  det_loss_fused<<<grid, TPB>>>(preds, targets, out);
}